// round 10
// baseline (speedup 1.0000x reference)
#include <cuda_runtime.h>
#include <cuda_bf16.h>

// Problem constants
#define B_SZ 64
#define C_SZ 3
#define H_SZ 512
#define W_SZ 512
#define GRID 4
// Flattened view: 64*3*512 = 98304 rows of 512 floats. slab = row>>7 in [0,768),
// slab = (b*3+c)*4 + gr  ->  b = slab/12, gr = slab&3.
#define NROWS 98304
#define NBLK 1184            // = 148 SMs * 8 CTAs: perfectly uniform residency
#define BIG_BLKS 32          // first 32 blocks take 84 rows, remaining 1152 take 83
#define SPLIT_ROW (BIG_BLKS * 84)   // 2688

// Scratch: per (block, slab-slot {0,1}, grid_col). Always written (zeros if a
// slot is unused) -> no zeroing between launches, exclusive -> deterministic.
__device__ float g_bpart[NBLK * 8];
__device__ unsigned int g_done = 0;   // reset by the last block each launch

__device__ __forceinline__ int row_start_of(int blk) {
    return blk < BIG_BLKS ? 84 * blk : SPLIT_ROW + 83 * (blk - BIG_BLKS);
}
__device__ __forceinline__ int blk_of_row(int r) {
    return r < SPLIT_ROW ? r / 84 : BIG_BLKS + (r - SPLIT_ROW) / 83;
}

// Warp-level deterministic reduce of 4 accumulators -> lane 0 writes smem.
__device__ __forceinline__ void warp_reduce_store(
    float a0, float a1, float a2, float a3, float* dst, int lane) {
    #pragma unroll
    for (int off = 16; off > 0; off >>= 1) {
        a0 += __shfl_down_sync(0xFFFFFFFFu, a0, off);
        a1 += __shfl_down_sync(0xFFFFFFFFu, a1, off);
        a2 += __shfl_down_sync(0xFFFFFFFFu, a2, off);
        a3 += __shfl_down_sync(0xFFFFFFFFu, a3, off);
    }
    if (lane == 0) { dst[0] = a0; dst[1] = a1; dst[2] = a2; dst[3] = a3; }
}

// 1184 blocks x 256 threads = exactly 8 CTAs resident on each of 148 SMs.
// Each block reduces 83-84 contiguous rows (512 floats each); rows cross at
// most one slab (128-row) boundary, handled by splitting the row loop into
// two segments, each flushed to its own scratch slot. Per row (128 float4),
// lane i loads positions i, i+32, i+64, i+96 -> grid columns 0..3.
__global__ void __launch_bounds__(256, 8) region_select_fused(
    const float* __restrict__ in, float* __restrict__ out) {
    const int blk = blockIdx.x;
    const int start = row_start_of(blk);
    const int nrows = blk < BIG_BLKS ? 84 : 83;
    const int end = start + nrows;
    const int bnd_raw = ((start >> 7) + 1) << 7;       // first row of next slab
    const int bnd = bnd_raw < end ? bnd_raw : end;     // clamp

    const int warp = threadIdx.x >> 5;
    const int lane = threadIdx.x & 31;

    __shared__ float s[8][8];   // [warp][slot*4 + gc]
    __shared__ bool s_last;

    // ---- Segment 0: rows [start, bnd) ----
    float a0 = 0.f, a1 = 0.f, a2 = 0.f, a3 = 0.f;
    int r = start + warp;
    #pragma unroll 1
    for (; r < bnd; r += 8) {
        const float4* __restrict__ row = (const float4*)in + (size_t)r * 128;
        float4 v0 = row[lane +  0];
        float4 v1 = row[lane + 32];
        float4 v2 = row[lane + 64];
        float4 v3 = row[lane + 96];
        a0 += (v0.x + v0.y) + (v0.z + v0.w);
        a1 += (v1.x + v1.y) + (v1.z + v1.w);
        a2 += (v2.x + v2.y) + (v2.z + v2.w);
        a3 += (v3.x + v3.y) + (v3.z + v3.w);
    }
    warp_reduce_store(a0, a1, a2, a3, &s[warp][0], lane);

    // ---- Segment 1: rows [bnd, end) (empty if no slab crossing) ----
    a0 = a1 = a2 = a3 = 0.f;
    #pragma unroll 1
    for (; r < end; r += 8) {
        const float4* __restrict__ row = (const float4*)in + (size_t)r * 128;
        float4 v0 = row[lane +  0];
        float4 v1 = row[lane + 32];
        float4 v2 = row[lane + 64];
        float4 v3 = row[lane + 96];
        a0 += (v0.x + v0.y) + (v0.z + v0.w);
        a1 += (v1.x + v1.y) + (v1.z + v1.w);
        a2 += (v2.x + v2.y) + (v2.z + v2.w);
        a3 += (v3.x + v3.y) + (v3.z + v3.w);
    }
    warp_reduce_store(a0, a1, a2, a3, &s[warp][4], lane);
    __syncthreads();

    if (threadIdx.x < 8) {                 // slot = tid>>2, gc = tid&3
        float sum = 0.f;
        #pragma unroll
        for (int w = 0; w < 8; ++w) sum += s[w][threadIdx.x];   // fixed order
        g_bpart[blk * 8 + threadIdx.x] = sum;
    }

    // Publish + vote on being last (R6's measured-best epilogue).
    __threadfence();
    if (threadIdx.x == 0) {
        unsigned int old = atomicAdd(&g_done, 1u);
        s_last = (old == (unsigned)(NBLK - 1));
    }
    __syncthreads();
    if (!s_last) return;

    // ---- Last block: selection (threads 0..63, one per batch) ----
    if (threadIdx.x == 0) g_done = 0;   // reset for next graph replay
    __threadfence();

    const int bb = threadIdx.x;
    if (bb < B_SZ) {
        // Blocks whose rows intersect batch bb (rows [1536*bb, 1536*bb+1536)).
        const int r_lo = bb * 1536;
        const int r_hi = r_lo + 1535;
        const int k_lo = blk_of_row(r_lo);
        const int k_hi = blk_of_row(r_hi);

        float cell[GRID][GRID];
        #pragma unroll
        for (int i = 0; i < GRID; ++i)
            #pragma unroll
            for (int j = 0; j < GRID; ++j) cell[i][j] = 0.f;

        for (int k = k_lo; k <= k_hi; ++k) {        // fixed order -> deterministic
            const int st = row_start_of(k);
            const int en = st + (k < BIG_BLKS ? 84 : 83);
            const int ss0 = st >> 7;
            const int ss1 = (en - 1) >> 7;
            if (ss0 / 12 == bb) {
                const int gr = ss0 & 3;
                #pragma unroll
                for (int gc = 0; gc < 4; ++gc) cell[gr][gc] += g_bpart[k * 8 + gc];
            }
            if (ss1 != ss0 && ss1 / 12 == bb) {
                const int gr = ss1 & 3;
                #pragma unroll
                for (int gc = 0; gc < 4; ++gc) cell[gr][gc] += g_bpart[k * 8 + 4 + gc];
            }
        }

        float w[4];
        #pragma unroll
        for (int wr = 0; wr < 2; ++wr) {
            #pragma unroll
            for (int wc = 0; wc < 2; ++wc) {
                float sum = 0.f;
                #pragma unroll
                for (int i = 0; i < 3; ++i)
                    #pragma unroll
                    for (int j = 0; j < 3; ++j)
                        sum += cell[wr + i][wc + j];
                w[wr * 2 + wc] = sum;
            }
        }

        int best = 0;
        float bv = w[0];
        #pragma unroll
        for (int i = 1; i < 4; ++i) {
            if (w[i] > bv) { bv = w[i]; best = i; }   // strict > = first-index tie-break
        }

        out[bb * 2 + 0] = (float)(best >> 1);   // row
        out[bb * 2 + 1] = (float)(best & 1);    // col
    }
}

extern "C" void kernel_launch(void* const* d_in, const int* in_sizes, int n_in,
                              void* d_out, int out_size) {
    const float* sampling_map = (const float*)d_in[0];
    float* out = (float*)d_out;

    region_select_fused<<<NBLK, 256>>>(sampling_map, out);
}

// round 12
// speedup vs baseline: 1.2723x; 1.2723x over previous
#include <cuda_runtime.h>
#include <cuda_bf16.h>

// Problem constants
#define B_SZ 64
#define C_SZ 3
#define H_SZ 512
#define W_SZ 512
#define GRID 4
#define GH (H_SZ / GRID)             // 128 rows per slab
#define NBLK (B_SZ * GRID * C_SZ)    // 768 blocks x 256 threads (best measured)

// Scratch: per (b, grid_row, channel, grid_col) partial sums.
// Every slot written exclusively by one block each launch -> no zeroing needed.
__device__ float g_part[B_SZ * GRID * C_SZ * GRID];
__device__ unsigned int g_done = 0;   // reset by the last block each launch

// R6 structure exactly, with ONE change: the release fence before the
// completion atomic is executed by thread 0 only (after __syncthreads
// establishes happens-before for the CTA's g_part stores), instead of by
// all 256 threads. Cuts ~196k fence instructions to 768 per launch.
__global__ void __launch_bounds__(256) region_select_fused(
    const float* __restrict__ in, float* __restrict__ out) {
    const int blk = blockIdx.x;              // [0, 768)
    const int c  = blk % C_SZ;
    const int gr = (blk / C_SZ) % GRID;
    const int b  = blk / (C_SZ * GRID);

    const size_t base_off = ((size_t)(b * C_SZ + c) * H_SZ + (size_t)gr * GH) * W_SZ;
    const float4* __restrict__ base = (const float4*)(in + base_off);
    // rows are 128 float4 wide

    const int warp = threadIdx.x >> 5;
    const int lane = threadIdx.x & 31;

    float a0 = 0.f, a1 = 0.f, a2 = 0.f, a3 = 0.f;

    #pragma unroll 1
    for (int r = warp; r < GH; r += 8) {
        const float4* __restrict__ row = base + (size_t)r * 128;
        float4 v0 = row[lane +  0];   // grid col 0
        float4 v1 = row[lane + 32];   // grid col 1
        float4 v2 = row[lane + 64];   // grid col 2
        float4 v3 = row[lane + 96];   // grid col 3
        a0 += (v0.x + v0.y) + (v0.z + v0.w);
        a1 += (v1.x + v1.y) + (v1.z + v1.w);
        a2 += (v2.x + v2.y) + (v2.z + v2.w);
        a3 += (v3.x + v3.y) + (v3.z + v3.w);
    }

    // Warp tree reduction (deterministic)
    #pragma unroll
    for (int off = 16; off > 0; off >>= 1) {
        a0 += __shfl_down_sync(0xFFFFFFFFu, a0, off);
        a1 += __shfl_down_sync(0xFFFFFFFFu, a1, off);
        a2 += __shfl_down_sync(0xFFFFFFFFu, a2, off);
        a3 += __shfl_down_sync(0xFFFFFFFFu, a3, off);
    }

    __shared__ float s[8][4];
    __shared__ bool s_last;
    if (lane == 0) {
        s[warp][0] = a0; s[warp][1] = a1; s[warp][2] = a2; s[warp][3] = a3;
    }
    __syncthreads();

    if (threadIdx.x < 4) {
        const int gc = threadIdx.x;
        float sum = 0.f;
        #pragma unroll
        for (int w = 0; w < 8; ++w) sum += s[w][gc];   // fixed order -> deterministic
        g_part[((b * GRID + gr) * C_SZ + c) * GRID + gc] = sum;
    }
    __syncthreads();   // g_part stores happen-before thread 0's fence

    if (threadIdx.x == 0) {
        __threadfence();                      // SINGLE-THREAD release fence
        unsigned int old = atomicAdd(&g_done, 1u);
        s_last = (old == (unsigned)(NBLK - 1));
    }
    __syncthreads();
    if (!s_last) return;

    // ---- Last block: selection (threads 0..63, one per batch) ----
    if (threadIdx.x == 0) g_done = 0;   // reset for next graph replay
    __threadfence();                    // acquire side: one block only

    const int bb = threadIdx.x;
    if (bb < B_SZ) {
        float cell[GRID][GRID];
        #pragma unroll
        for (int gr2 = 0; gr2 < GRID; ++gr2) {
            #pragma unroll
            for (int gc = 0; gc < GRID; ++gc) {
                float sum = 0.f;
                #pragma unroll
                for (int cc = 0; cc < C_SZ; ++cc)
                    sum += g_part[((bb * GRID + gr2) * C_SZ + cc) * GRID + gc];
                cell[gr2][gc] = sum;
            }
        }

        float w[4];
        #pragma unroll
        for (int wr = 0; wr < 2; ++wr) {
            #pragma unroll
            for (int wc = 0; wc < 2; ++wc) {
                float sum = 0.f;
                #pragma unroll
                for (int i = 0; i < 3; ++i)
                    #pragma unroll
                    for (int j = 0; j < 3; ++j)
                        sum += cell[wr + i][wc + j];
                w[wr * 2 + wc] = sum;
            }
        }

        int best = 0;
        float bv = w[0];
        #pragma unroll
        for (int i = 1; i < 4; ++i) {
            if (w[i] > bv) { bv = w[i]; best = i; }   // strict > = first-index tie-break
        }

        out[bb * 2 + 0] = (float)(best >> 1);   // row
        out[bb * 2 + 1] = (float)(best & 1);    // col
    }
}

extern "C" void kernel_launch(void* const* d_in, const int* in_sizes, int n_in,
                              void* d_out, int out_size) {
    const float* sampling_map = (const float*)d_in[0];
    float* out = (float*)d_out;

    region_select_fused<<<NBLK, 256>>>(sampling_map, out);
}